// round 1
// baseline (speedup 1.0000x reference)
#include <cuda_runtime.h>

#define Bn    4
#define Ln    1024
#define Un    1024
#define Hn    16
#define Dn    64
#define MREL  129
#define BH    (Bn*Hn)         // 64
#define SCALE 0.125f          // 1/sqrt(64)

// ---------------- scratch (static device globals; no allocation) -------------
__device__ float g_q[Bn*Ln*Un];            // [b,l, h*64+d]   16.8 MB
__device__ float g_k[Bn*Ln*Un];
__device__ float g_v[Bn*Ln*Un];
__device__ float g_qm[BH*Ln*MREL];         // [bh, l, m]      33.8 MB
__device__ float g_attn[BH*Ln*Ln];         // [bh, i, j]      268 MB
__device__ float g_o[Bn*Ln*Un];            // pre-projection out

// ---------------- generic tiled fp32 GEMM: C[M,N] = A[M,K] @ B[K,N] (+bias) --
// 64x64 tile, 256 threads, 4x4 per thread, TK=16
__global__ __launch_bounds__(256) void gemm64(const float* __restrict__ A,
                                              const float* __restrict__ Bm,
                                              const float* __restrict__ bias,
                                              float* __restrict__ C,
                                              int Kdim, int Ndim)
{
    __shared__ float As[16][64];   // As[k][m]
    __shared__ float Bs[16][64];   // Bs[k][n]
    const int t  = threadIdx.x;
    const int tx = t & 15, ty = t >> 4;
    const int row0 = blockIdx.y << 6, col0 = blockIdx.x << 6;

    float acc[4][4] = {};

    const int ar = t >> 2, ak = (t & 3) << 2;     // A loader: row ar, 4 k's at ak
    const int bk = t >> 4, bn = (t & 15) << 2;    // B loader
    const float* Aptr = A + (size_t)(row0 + ar) * Kdim + ak;
    const float* Bptr = Bm + (size_t)bk * Ndim + col0 + bn;

    for (int k0 = 0; k0 < Kdim; k0 += 16) {
        float4 a4 = *(const float4*)(Aptr + k0);
        As[ak + 0][ar] = a4.x; As[ak + 1][ar] = a4.y;
        As[ak + 2][ar] = a4.z; As[ak + 3][ar] = a4.w;
        *(float4*)&Bs[bk][bn] = *(const float4*)(Bptr + (size_t)k0 * Ndim);
        __syncthreads();
#pragma unroll
        for (int k = 0; k < 16; k++) {
            float4 av = *(const float4*)&As[k][ty << 2];
            float4 bv = *(const float4*)&Bs[k][tx << 2];
            acc[0][0] += av.x*bv.x; acc[0][1] += av.x*bv.y; acc[0][2] += av.x*bv.z; acc[0][3] += av.x*bv.w;
            acc[1][0] += av.y*bv.x; acc[1][1] += av.y*bv.y; acc[1][2] += av.y*bv.z; acc[1][3] += av.y*bv.w;
            acc[2][0] += av.z*bv.x; acc[2][1] += av.z*bv.y; acc[2][2] += av.z*bv.z; acc[2][3] += av.z*bv.w;
            acc[3][0] += av.w*bv.x; acc[3][1] += av.w*bv.y; acc[3][2] += av.w*bv.z; acc[3][3] += av.w*bv.w;
        }
        __syncthreads();
    }
#pragma unroll
    for (int i = 0; i < 4; i++) {
        float4 r = make_float4(acc[i][0], acc[i][1], acc[i][2], acc[i][3]);
        if (bias) {
            float4 bb = *(const float4*)(bias + col0 + (tx << 2));
            r.x += bb.x; r.y += bb.y; r.z += bb.z; r.w += bb.w;
        }
        *(float4*)(C + (size_t)(row0 + (ty << 2) + i) * Ndim + col0 + (tx << 2)) = r;
    }
}

// ---------------- qm[bh,l,m] = sum_d q[b,l,h*64+d] * ek[h,m,d] ---------------
// block: 256 threads, 32 query rows; ek[h] cached in smem
__global__ __launch_bounds__(256) void qm_kernel(const float* __restrict__ ek)
{
    __shared__ float Qs[32][65];
    __shared__ float Es[MREL][65];
    const int t  = threadIdx.x;
    const int bh = blockIdx.y;
    const int b  = bh >> 4, h = bh & 15;
    const int i0 = blockIdx.x << 5;

    for (int v = t; v < 512; v += 256) {               // 32x64 Q
        int r = v >> 4, dv = (v & 15) << 2;
        float4 a = *(const float4*)(g_q + ((size_t)((b << 10) + i0 + r) << 10) + (h << 6) + dv);
        Qs[r][dv] = a.x; Qs[r][dv+1] = a.y; Qs[r][dv+2] = a.z; Qs[r][dv+3] = a.w;
    }
    for (int v = t; v < MREL * 16; v += 256) {         // 129x64 ek[h]
        int m = v >> 4, dv = (v & 15) << 2;
        float4 a = *(const float4*)(ek + ((size_t)(h * MREL + m) << 6) + dv);
        Es[m][dv] = a.x; Es[m][dv+1] = a.y; Es[m][dv+2] = a.z; Es[m][dv+3] = a.w;
    }
    __syncthreads();

    for (int v = t; v < 32 * MREL; v += 256) {
        int r = v & 31, m = v >> 5;
        float acc = 0.f;
#pragma unroll 16
        for (int d = 0; d < 64; d++) acc += Qs[r][d] * Es[m][d];
        g_qm[(size_t)((bh << 10) + i0 + r) * MREL + m] = acc;
    }
}

// ---------------- logits: attn[bh,i,j] = (q.k + qm gather)*scale + mask ------
__global__ __launch_bounds__(256) void logits_kernel(const float* __restrict__ mask)
{
    __shared__ float Qs[64][65];
    __shared__ float Ks[64][65];
    const int t  = threadIdx.x;
    const int tx = t & 15, ty = t >> 4;
    const int bh = blockIdx.z, b = bh >> 4, h = bh & 15;
    const int i0 = blockIdx.y << 6, j0 = blockIdx.x << 6;

    for (int v = t; v < 1024; v += 256) {
        int r = v >> 4, dv = (v & 15) << 2;
        float4 a = *(const float4*)(g_q + ((size_t)((b << 10) + i0 + r) << 10) + (h << 6) + dv);
        Qs[r][dv] = a.x; Qs[r][dv+1] = a.y; Qs[r][dv+2] = a.z; Qs[r][dv+3] = a.w;
        float4 c = *(const float4*)(g_k + ((size_t)((b << 10) + j0 + r) << 10) + (h << 6) + dv);
        Ks[r][dv] = c.x; Ks[r][dv+1] = c.y; Ks[r][dv+2] = c.z; Ks[r][dv+3] = c.w;
    }
    __syncthreads();

    float acc[4][4] = {};
#pragma unroll 16
    for (int d = 0; d < 64; d++) {
        float a0 = Qs[ty][d], a1 = Qs[ty+16][d], a2 = Qs[ty+32][d], a3 = Qs[ty+48][d];
        float b0 = Ks[tx][d], b1 = Ks[tx+16][d], b2 = Ks[tx+32][d], b3 = Ks[tx+48][d];
        acc[0][0]+=a0*b0; acc[0][1]+=a0*b1; acc[0][2]+=a0*b2; acc[0][3]+=a0*b3;
        acc[1][0]+=a1*b0; acc[1][1]+=a1*b1; acc[1][2]+=a1*b2; acc[1][3]+=a1*b3;
        acc[2][0]+=a2*b0; acc[2][1]+=a2*b1; acc[2][2]+=a2*b2; acc[2][3]+=a2*b3;
        acc[3][0]+=a3*b0; acc[3][1]+=a3*b1; acc[3][2]+=a3*b2; acc[3][3]+=a3*b3;
    }

#pragma unroll
    for (int ii = 0; ii < 4; ii++) {
        const int i = i0 + ty + (ii << 4);
        const float* qrow = g_qm + (size_t)((bh << 10) + i) * MREL;
#pragma unroll
        for (int jj = 0; jj < 4; jj++) {
            const int j = j0 + tx + (jj << 4);
            int off = j - i;
            off = off < -64 ? -64 : (off > 64 ? 64 : off);
            float val = (acc[ii][jj] + qrow[off + 64]) * SCALE + mask[(b << 10) + j] * -1e9f;
            g_attn[((size_t)((bh << 10) + i) << 10) + j] = val;
        }
    }
}

// ---------------- row-wise softmax over g_attn -------------------------------
__global__ __launch_bounds__(256) void softmax_kernel()
{
    const size_t row = blockIdx.x;
    float* p = g_attn + (row << 10);
    const int t = threadIdx.x, lane = t & 31, w = t >> 5;

    float v0 = p[t], v1 = p[t + 256], v2 = p[t + 512], v3 = p[t + 768];
    float m = fmaxf(fmaxf(v0, v1), fmaxf(v2, v3));
#pragma unroll
    for (int o = 16; o; o >>= 1) m = fmaxf(m, __shfl_xor_sync(0xffffffffu, m, o));
    __shared__ float smax[8], ssum[8];
    if (lane == 0) smax[w] = m;
    __syncthreads();
    if (t == 0) {
        float mm = smax[0];
#pragma unroll
        for (int i = 1; i < 8; i++) mm = fmaxf(mm, smax[i]);
        smax[0] = mm;
    }
    __syncthreads();
    const float rm = smax[0];
    v0 = __expf(v0 - rm); v1 = __expf(v1 - rm); v2 = __expf(v2 - rm); v3 = __expf(v3 - rm);
    float s = v0 + v1 + v2 + v3;
#pragma unroll
    for (int o = 16; o; o >>= 1) s += __shfl_xor_sync(0xffffffffu, s, o);
    if (lane == 0) ssum[w] = s;
    __syncthreads();
    if (t == 0) {
        float tt = 0.f;
#pragma unroll
        for (int i = 0; i < 8; i++) tt += ssum[i];
        ssum[0] = tt;
    }
    __syncthreads();
    const float inv = 1.0f / ssum[0];
    p[t] = v0 * inv; p[t + 256] = v1 * inv; p[t + 512] = v2 * inv; p[t + 768] = v3 * inv;
}

// ---------------- O = attn @ V (per head) ------------------------------------
__global__ __launch_bounds__(256) void av_kernel()
{
    __shared__ float As[64][65];
    __shared__ float Vs[64][65];
    const int t  = threadIdx.x;
    const int tx = t & 15, ty = t >> 4;
    const int bh = blockIdx.y, b = bh >> 4, h = bh & 15;
    const int i0 = blockIdx.x << 6;

    float acc[4][4] = {};
    for (int j0 = 0; j0 < Ln; j0 += 64) {
        for (int v = t; v < 1024; v += 256) {
            int r = v >> 4, dv = (v & 15) << 2;
            float4 a = *(const float4*)(g_attn + ((size_t)((bh << 10) + i0 + r) << 10) + j0 + dv);
            As[r][dv] = a.x; As[r][dv+1] = a.y; As[r][dv+2] = a.z; As[r][dv+3] = a.w;
            float4 c = *(const float4*)(g_v + ((size_t)((b << 10) + j0 + r) << 10) + (h << 6) + dv);
            Vs[r][dv] = c.x; Vs[r][dv+1] = c.y; Vs[r][dv+2] = c.z; Vs[r][dv+3] = c.w;
        }
        __syncthreads();
#pragma unroll 16
        for (int j = 0; j < 64; j++) {
            float a0 = As[ty][j], a1 = As[ty+16][j], a2 = As[ty+32][j], a3 = As[ty+48][j];
            float b0 = Vs[j][tx], b1 = Vs[j][tx+16], b2 = Vs[j][tx+32], b3 = Vs[j][tx+48];
            acc[0][0]+=a0*b0; acc[0][1]+=a0*b1; acc[0][2]+=a0*b2; acc[0][3]+=a0*b3;
            acc[1][0]+=a1*b0; acc[1][1]+=a1*b1; acc[1][2]+=a1*b2; acc[1][3]+=a1*b3;
            acc[2][0]+=a2*b0; acc[2][1]+=a2*b1; acc[2][2]+=a2*b2; acc[2][3]+=a2*b3;
            acc[3][0]+=a3*b0; acc[3][1]+=a3*b1; acc[3][2]+=a3*b2; acc[3][3]+=a3*b3;
        }
        __syncthreads();
    }
#pragma unroll
    for (int ii = 0; ii < 4; ii++)
#pragma unroll
        for (int dd = 0; dd < 4; dd++)
            g_o[((size_t)((b << 10) + i0 + ty + (ii << 4)) << 10) + (h << 6) + tx + (dd << 4)] = acc[ii][dd];
}

// ---------------- wr buckets + wr @ ev, accumulated into g_o -----------------
// one block (128 threads) per (bh, i)
__global__ __launch_bounds__(128) void wrev_kernel(const float* __restrict__ ev)
{
    const int gb = blockIdx.x;            // (bh<<10) + i
    const int i  = gb & 1023;
    const int bh = gb >> 10;
    const int h  = bh & 15, b = bh >> 4;
    const float* row = g_attn + ((size_t)gb << 10);
    const int t = threadIdx.x, lane = t & 31, w = t >> 5;

    __shared__ float wr[MREL];
    __shared__ float rl[4], rh[4];

    // middle buckets m=1..127 : single j = i + m - 64
    if (t >= 1 && t <= 127) {
        int j = i + t - 64;
        wr[t] = (j >= 0 && j < Ln) ? row[j] : 0.f;
    }
    // edge buckets: m=0 sums j<=i-64 ; m=128 sums j>=i+64
    float lo = 0.f, hi = 0.f;
    for (int j = t; j <= i - 64; j += 128) lo += row[j];
    for (int j = i + 64 + t; j < Ln; j += 128) hi += row[j];
#pragma unroll
    for (int o = 16; o; o >>= 1) {
        lo += __shfl_xor_sync(0xffffffffu, lo, o);
        hi += __shfl_xor_sync(0xffffffffu, hi, o);
    }
    if (lane == 0) { rl[w] = lo; rh[w] = hi; }
    __syncthreads();
    if (t == 0) wr[0]   = rl[0] + rl[1] + rl[2] + rl[3];
    if (t == 32) wr[128] = rh[0] + rh[1] + rh[2] + rh[3];
    __syncthreads();

    if (t < 64) {
        const float* e = ev + ((size_t)h * MREL << 6) + t;   // ev[h, m, d=t]
        float acc = 0.f;
#pragma unroll 16
        for (int m = 0; m < MREL; m++) acc += wr[m] * e[(size_t)m << 6];
        g_o[((size_t)((b << 10) + i) << 10) + (h << 6) + t] += acc;
    }
}

// -----------------------------------------------------------------------------
extern "C" void kernel_launch(void* const* d_in, const int* in_sizes, int n_in,
                              void* d_out, int out_size)
{
    const float* x    = (const float*)d_in[0];
    const float* mask = (const float*)d_in[1];
    const float* wq   = (const float*)d_in[2];
    const float* wk   = (const float*)d_in[3];
    const float* wv   = (const float*)d_in[4];
    const float* wo   = (const float*)d_in[5];
    const float* bo   = (const float*)d_in[6];
    const float* ek   = (const float*)d_in[7];
    const float* ev   = (const float*)d_in[8];
    float* out = (float*)d_out;

    float *pq, *pk, *pv, *po;
    cudaGetSymbolAddress((void**)&pq, g_q);
    cudaGetSymbolAddress((void**)&pk, g_k);
    cudaGetSymbolAddress((void**)&pv, g_v);
    cudaGetSymbolAddress((void**)&po, g_o);

    const dim3 gproj(Un / 64, (Bn * Ln) / 64);      // (16, 64)

    // Q, K, V projections
    gemm64<<<gproj, 256>>>(x, wq, nullptr, pq, Un, Un);
    gemm64<<<gproj, 256>>>(x, wk, nullptr, pk, Un, Un);
    gemm64<<<gproj, 256>>>(x, wv, nullptr, pv, Un, Un);

    // q . ek over relative buckets
    qm_kernel<<<dim3(Ln / 32, BH), 256>>>(ek);

    // logits (QK^T + rel gather, scaled + masked)
    logits_kernel<<<dim3(Ln / 64, Ln / 64, BH), 256>>>(mask);

    // softmax
    softmax_kernel<<<BH * Ln, 256>>>();

    // attn @ V
    av_kernel<<<dim3(Ln / 64, BH), 256>>>();

    // relative-value term
    wrev_kernel<<<BH * Ln, 128>>>(ev);

    // output projection + bias
    gemm64<<<gproj, 256>>>(po, wo, bo, out, Un, Un);
}

// round 2
// speedup vs baseline: 1.0018x; 1.0018x over previous
#include <cuda_runtime.h>

#define Bn    4
#define Ln    1024
#define Un    1024
#define Hn    16
#define Dn    64
#define MREL  129
#define BH    (Bn*Hn)         // 64
#define SCALE 0.125f          // 1/sqrt(64)

// ---------------- scratch (static device globals; no allocation) -------------
__device__ float g_q[Bn*Ln*Un];            // [b,l, h*64+d]   16.8 MB
__device__ float g_k[Bn*Ln*Un];
__device__ float g_v[Bn*Ln*Un];
__device__ float g_qm[BH*Ln*MREL];         // [bh, l, m]      33.8 MB
__device__ float g_attn[BH*Ln*Ln];         // [bh, i, j]      268 MB
__device__ float g_o[Bn*Ln*Un];            // pre-projection out

// ---------------- generic tiled fp32 GEMM: C[M,N] = A[M,K] @ B[K,N] (+bias) --
// 64x64 tile, 256 threads, 4x4 per thread, TK=16
__global__ __launch_bounds__(256) void gemm64(const float* __restrict__ A,
                                              const float* __restrict__ Bm,
                                              const float* __restrict__ bias,
                                              float* __restrict__ C,
                                              int Kdim, int Ndim)
{
    __shared__ float As[16][64];   // As[k][m]
    __shared__ float Bs[16][64];   // Bs[k][n]
    const int t  = threadIdx.x;
    const int tx = t & 15, ty = t >> 4;
    const int row0 = blockIdx.y << 6, col0 = blockIdx.x << 6;

    float acc[4][4] = {};

    const int ar = t >> 2, ak = (t & 3) << 2;     // A loader: row ar, 4 k's at ak
    const int bk = t >> 4, bn = (t & 15) << 2;    // B loader
    const float* Aptr = A + (size_t)(row0 + ar) * Kdim + ak;
    const float* Bptr = Bm + (size_t)bk * Ndim + col0 + bn;

    for (int k0 = 0; k0 < Kdim; k0 += 16) {
        float4 a4 = *(const float4*)(Aptr + k0);
        As[ak + 0][ar] = a4.x; As[ak + 1][ar] = a4.y;
        As[ak + 2][ar] = a4.z; As[ak + 3][ar] = a4.w;
        *(float4*)&Bs[bk][bn] = *(const float4*)(Bptr + (size_t)k0 * Ndim);
        __syncthreads();
#pragma unroll
        for (int k = 0; k < 16; k++) {
            float4 av = *(const float4*)&As[k][ty << 2];
            float4 bv = *(const float4*)&Bs[k][tx << 2];
            acc[0][0] += av.x*bv.x; acc[0][1] += av.x*bv.y; acc[0][2] += av.x*bv.z; acc[0][3] += av.x*bv.w;
            acc[1][0] += av.y*bv.x; acc[1][1] += av.y*bv.y; acc[1][2] += av.y*bv.z; acc[1][3] += av.y*bv.w;
            acc[2][0] += av.z*bv.x; acc[2][1] += av.z*bv.y; acc[2][2] += av.z*bv.z; acc[2][3] += av.z*bv.w;
            acc[3][0] += av.w*bv.x; acc[3][1] += av.w*bv.y; acc[3][2] += av.w*bv.z; acc[3][3] += av.w*bv.w;
        }
        __syncthreads();
    }
#pragma unroll
    for (int i = 0; i < 4; i++) {
        float4 r = make_float4(acc[i][0], acc[i][1], acc[i][2], acc[i][3]);
        if (bias) {
            float4 bb = *(const float4*)(bias + col0 + (tx << 2));
            r.x += bb.x; r.y += bb.y; r.z += bb.z; r.w += bb.w;
        }
        *(float4*)(C + (size_t)(row0 + (ty << 2) + i) * Ndim + col0 + (tx << 2)) = r;
    }
}

// ---------------- qm[bh,l,m] = sum_d q[b,l,h*64+d] * ek[h,m,d] ---------------
// block: 256 threads, 32 query rows; ek[h] cached in smem
__global__ __launch_bounds__(256) void qm_kernel(const float* __restrict__ ek)
{
    __shared__ float Qs[32][65];
    __shared__ float Es[MREL][65];
    const int t  = threadIdx.x;
    const int bh = blockIdx.y;
    const int b  = bh >> 4, h = bh & 15;
    const int i0 = blockIdx.x << 5;

    for (int v = t; v < 512; v += 256) {               // 32x64 Q
        int r = v >> 4, dv = (v & 15) << 2;
        float4 a = *(const float4*)(g_q + ((size_t)((b << 10) + i0 + r) << 10) + (h << 6) + dv);
        Qs[r][dv] = a.x; Qs[r][dv+1] = a.y; Qs[r][dv+2] = a.z; Qs[r][dv+3] = a.w;
    }
    for (int v = t; v < MREL * 16; v += 256) {         // 129x64 ek[h]
        int m = v >> 4, dv = (v & 15) << 2;
        float4 a = *(const float4*)(ek + ((size_t)(h * MREL + m) << 6) + dv);
        Es[m][dv] = a.x; Es[m][dv+1] = a.y; Es[m][dv+2] = a.z; Es[m][dv+3] = a.w;
    }
    __syncthreads();

    for (int v = t; v < 32 * MREL; v += 256) {
        int r = v & 31, m = v >> 5;
        float acc = 0.f;
#pragma unroll 16
        for (int d = 0; d < 64; d++) acc += Qs[r][d] * Es[m][d];
        g_qm[(size_t)((bh << 10) + i0 + r) * MREL + m] = acc;
    }
}

// ---------------- logits: attn[bh,i,j] = (q.k + qm gather)*scale + mask ------
__global__ __launch_bounds__(256) void logits_kernel(const float* __restrict__ mask)
{
    __shared__ float Qs[64][65];
    __shared__ float Ks[64][65];
    const int t  = threadIdx.x;
    const int tx = t & 15, ty = t >> 4;
    const int bh = blockIdx.z, b = bh >> 4, h = bh & 15;
    const int i0 = blockIdx.y << 6, j0 = blockIdx.x << 6;

    for (int v = t; v < 1024; v += 256) {
        int r = v >> 4, dv = (v & 15) << 2;
        float4 a = *(const float4*)(g_q + ((size_t)((b << 10) + i0 + r) << 10) + (h << 6) + dv);
        Qs[r][dv] = a.x; Qs[r][dv+1] = a.y; Qs[r][dv+2] = a.z; Qs[r][dv+3] = a.w;
        float4 c = *(const float4*)(g_k + ((size_t)((b << 10) + j0 + r) << 10) + (h << 6) + dv);
        Ks[r][dv] = c.x; Ks[r][dv+1] = c.y; Ks[r][dv+2] = c.z; Ks[r][dv+3] = c.w;
    }
    __syncthreads();

    float acc[4][4] = {};
#pragma unroll 16
    for (int d = 0; d < 64; d++) {
        float a0 = Qs[ty][d], a1 = Qs[ty+16][d], a2 = Qs[ty+32][d], a3 = Qs[ty+48][d];
        float b0 = Ks[tx][d], b1 = Ks[tx+16][d], b2 = Ks[tx+32][d], b3 = Ks[tx+48][d];
        acc[0][0]+=a0*b0; acc[0][1]+=a0*b1; acc[0][2]+=a0*b2; acc[0][3]+=a0*b3;
        acc[1][0]+=a1*b0; acc[1][1]+=a1*b1; acc[1][2]+=a1*b2; acc[1][3]+=a1*b3;
        acc[2][0]+=a2*b0; acc[2][1]+=a2*b1; acc[2][2]+=a2*b2; acc[2][3]+=a2*b3;
        acc[3][0]+=a3*b0; acc[3][1]+=a3*b1; acc[3][2]+=a3*b2; acc[3][3]+=a3*b3;
    }

#pragma unroll
    for (int ii = 0; ii < 4; ii++) {
        const int i = i0 + ty + (ii << 4);
        const float* qrow = g_qm + (size_t)((bh << 10) + i) * MREL;
#pragma unroll
        for (int jj = 0; jj < 4; jj++) {
            const int j = j0 + tx + (jj << 4);
            int off = j - i;
            off = off < -64 ? -64 : (off > 64 ? 64 : off);
            float val = (acc[ii][jj] + qrow[off + 64]) * SCALE + mask[(b << 10) + j] * -1e9f;
            g_attn[((size_t)((bh << 10) + i) << 10) + j] = val;
        }
    }
}

// ---------------- row-wise softmax over g_attn -------------------------------
__global__ __launch_bounds__(256) void softmax_kernel()
{
    const size_t row = blockIdx.x;
    float* p = g_attn + (row << 10);
    const int t = threadIdx.x, lane = t & 31, w = t >> 5;

    float v0 = p[t], v1 = p[t + 256], v2 = p[t + 512], v3 = p[t + 768];
    float m = fmaxf(fmaxf(v0, v1), fmaxf(v2, v3));
#pragma unroll
    for (int o = 16; o; o >>= 1) m = fmaxf(m, __shfl_xor_sync(0xffffffffu, m, o));
    __shared__ float smax[8], ssum[8];
    if (lane == 0) smax[w] = m;
    __syncthreads();
    if (t == 0) {
        float mm = smax[0];
#pragma unroll
        for (int i = 1; i < 8; i++) mm = fmaxf(mm, smax[i]);
        smax[0] = mm;
    }
    __syncthreads();
    const float rm = smax[0];
    v0 = __expf(v0 - rm); v1 = __expf(v1 - rm); v2 = __expf(v2 - rm); v3 = __expf(v3 - rm);
    float s = v0 + v1 + v2 + v3;
#pragma unroll
    for (int o = 16; o; o >>= 1) s += __shfl_xor_sync(0xffffffffu, s, o);
    if (lane == 0) ssum[w] = s;
    __syncthreads();
    if (t == 0) {
        float tt = 0.f;
#pragma unroll
        for (int i = 0; i < 8; i++) tt += ssum[i];
        ssum[0] = tt;
    }
    __syncthreads();
    const float inv = 1.0f / ssum[0];
    p[t] = v0 * inv; p[t + 256] = v1 * inv; p[t + 512] = v2 * inv; p[t + 768] = v3 * inv;
}

// ---------------- O = attn @ V (per head) ------------------------------------
__global__ __launch_bounds__(256) void av_kernel()
{
    __shared__ float As[64][65];
    __shared__ float Vs[64][65];
    const int t  = threadIdx.x;
    const int tx = t & 15, ty = t >> 4;
    const int bh = blockIdx.y, b = bh >> 4, h = bh & 15;
    const int i0 = blockIdx.x << 6;

    float acc[4][4] = {};
    for (int j0 = 0; j0 < Ln; j0 += 64) {
        for (int v = t; v < 1024; v += 256) {
            int r = v >> 4, dv = (v & 15) << 2;
            float4 a = *(const float4*)(g_attn + ((size_t)((bh << 10) + i0 + r) << 10) + j0 + dv);
            As[r][dv] = a.x; As[r][dv+1] = a.y; As[r][dv+2] = a.z; As[r][dv+3] = a.w;
            float4 c = *(const float4*)(g_v + ((size_t)((b << 10) + j0 + r) << 10) + (h << 6) + dv);
            Vs[r][dv] = c.x; Vs[r][dv+1] = c.y; Vs[r][dv+2] = c.z; Vs[r][dv+3] = c.w;
        }
        __syncthreads();
#pragma unroll 16
        for (int j = 0; j < 64; j++) {
            float a0 = As[ty][j], a1 = As[ty+16][j], a2 = As[ty+32][j], a3 = As[ty+48][j];
            float b0 = Vs[j][tx], b1 = Vs[j][tx+16], b2 = Vs[j][tx+32], b3 = Vs[j][tx+48];
            acc[0][0]+=a0*b0; acc[0][1]+=a0*b1; acc[0][2]+=a0*b2; acc[0][3]+=a0*b3;
            acc[1][0]+=a1*b0; acc[1][1]+=a1*b1; acc[1][2]+=a1*b2; acc[1][3]+=a1*b3;
            acc[2][0]+=a2*b0; acc[2][1]+=a2*b1; acc[2][2]+=a2*b2; acc[2][3]+=a2*b3;
            acc[3][0]+=a3*b0; acc[3][1]+=a3*b1; acc[3][2]+=a3*b2; acc[3][3]+=a3*b3;
        }
        __syncthreads();
    }
#pragma unroll
    for (int ii = 0; ii < 4; ii++)
#pragma unroll
        for (int dd = 0; dd < 4; dd++)
            g_o[((size_t)((b << 10) + i0 + ty + (ii << 4)) << 10) + (h << 6) + tx + (dd << 4)] = acc[ii][dd];
}

// ---------------- wr buckets + wr @ ev, accumulated into g_o -----------------
// one block (128 threads) per (bh, i)
__global__ __launch_bounds__(128) void wrev_kernel(const float* __restrict__ ev)
{
    const int gb = blockIdx.x;            // (bh<<10) + i
    const int i  = gb & 1023;
    const int bh = gb >> 10;
    const int h  = bh & 15, b = bh >> 4;
    const float* row = g_attn + ((size_t)gb << 10);
    const int t = threadIdx.x, lane = t & 31, w = t >> 5;

    __shared__ float wr[MREL];
    __shared__ float rl[4], rh[4];

    // middle buckets m=1..127 : single j = i + m - 64
    if (t >= 1 && t <= 127) {
        int j = i + t - 64;
        wr[t] = (j >= 0 && j < Ln) ? row[j] : 0.f;
    }
    // edge buckets: m=0 sums j<=i-64 ; m=128 sums j>=i+64
    float lo = 0.f, hi = 0.f;
    for (int j = t; j <= i - 64; j += 128) lo += row[j];
    for (int j = i + 64 + t; j < Ln; j += 128) hi += row[j];
#pragma unroll
    for (int o = 16; o; o >>= 1) {
        lo += __shfl_xor_sync(0xffffffffu, lo, o);
        hi += __shfl_xor_sync(0xffffffffu, hi, o);
    }
    if (lane == 0) { rl[w] = lo; rh[w] = hi; }
    __syncthreads();
    if (t == 0) wr[0]   = rl[0] + rl[1] + rl[2] + rl[3];
    if (t == 32) wr[128] = rh[0] + rh[1] + rh[2] + rh[3];
    __syncthreads();

    if (t < 64) {
        const float* e = ev + ((size_t)h * MREL << 6) + t;   // ev[h, m, d=t]
        float acc = 0.f;
#pragma unroll 16
        for (int m = 0; m < MREL; m++) acc += wr[m] * e[(size_t)m << 6];
        g_o[((size_t)((b << 10) + i) << 10) + (h << 6) + t] += acc;
    }
}

// -----------------------------------------------------------------------------
extern "C" void kernel_launch(void* const* d_in, const int* in_sizes, int n_in,
                              void* d_out, int out_size)
{
    const float* x    = (const float*)d_in[0];
    const float* mask = (const float*)d_in[1];
    const float* wq   = (const float*)d_in[2];
    const float* wk   = (const float*)d_in[3];
    const float* wv   = (const float*)d_in[4];
    const float* wo   = (const float*)d_in[5];
    const float* bo   = (const float*)d_in[6];
    const float* ek   = (const float*)d_in[7];
    const float* ev   = (const float*)d_in[8];
    float* out = (float*)d_out;

    float *pq, *pk, *pv, *po;
    cudaGetSymbolAddress((void**)&pq, g_q);
    cudaGetSymbolAddress((void**)&pk, g_k);
    cudaGetSymbolAddress((void**)&pv, g_v);
    cudaGetSymbolAddress((void**)&po, g_o);

    const dim3 gproj(Un / 64, (Bn * Ln) / 64);      // (16, 64)

    // Q, K, V projections
    gemm64<<<gproj, 256>>>(x, wq, nullptr, pq, Un, Un);
    gemm64<<<gproj, 256>>>(x, wk, nullptr, pk, Un, Un);
    gemm64<<<gproj, 256>>>(x, wv, nullptr, pv, Un, Un);

    // q . ek over relative buckets
    qm_kernel<<<dim3(Ln / 32, BH), 256>>>(ek);

    // logits (QK^T + rel gather, scaled + masked)
    logits_kernel<<<dim3(Ln / 64, Ln / 64, BH), 256>>>(mask);

    // softmax
    softmax_kernel<<<BH * Ln, 256>>>();

    // attn @ V
    av_kernel<<<dim3(Ln / 64, BH), 256>>>();

    // relative-value term
    wrev_kernel<<<BH * Ln, 128>>>(ev);

    // output projection + bias
    gemm64<<<gproj, 256>>>(po, wo, bo, out, Un, Un);
}

// round 4
// speedup vs baseline: 2.8066x; 2.8016x over previous
#include <cuda_runtime.h>
#include <cuda_bf16.h>
#include <cstdint>

#define Bn 4
#define Ln 1024
#define Un 1024
#define Hn 16
#define Dn 64
#define MREL 129
#define BHn 64
#define SCALE 0.125f
typedef __nv_bfloat16 bf;

// ---------------- static device scratch (no allocation) ----------------------
__device__ __align__(128) bf g_xh[Bn*Ln*Un], g_xl[Bn*Ln*Un];
__device__ __align__(128) bf g_wth[4*Un*Un], g_wtl[4*Un*Un];       // W^T, [n,k]
__device__ __align__(128) bf g_ekh[Hn*MREL*Dn], g_ekl[Hn*MREL*Dn]; // [h,m,d]
__device__ __align__(128) bf g_evth[Hn*Dn*192], g_evtl[Hn*Dn*192]; // ev^T pad 192
__device__ __align__(128) bf g_qh[Bn*Ln*Un], g_ql[Bn*Ln*Un];
__device__ __align__(128) bf g_kh[Bn*Ln*Un], g_kl[Bn*Ln*Un];
__device__ __align__(128) bf g_vh[Bn*Ln*Un], g_vl[Bn*Ln*Un];
__device__ __align__(128) bf g_vth[BHn*Dn*Ln], g_vtl[BHn*Dn*Ln];   // [bh,d,l]
__device__ __align__(128) float g_qm[(size_t)BHn*Ln*MREL];
__device__ __align__(128) float g_logit[(size_t)BHn*Ln*Ln];        // 268MB
__device__ __align__(128) bf g_ah[(size_t)BHn*Ln*Ln], g_al[(size_t)BHn*Ln*Ln];
__device__ __align__(128) bf g_wrh[(size_t)BHn*Ln*192], g_wrl[(size_t)BHn*Ln*192];
__device__ __align__(128) bf g_oh[Bn*Ln*Un], g_ol[Bn*Ln*Un];

// ---------------- helpers ----------------------------------------------------
__device__ __forceinline__ uint32_t smem_u32(const void* p){
    uint32_t a;
    asm("{ .reg .u64 t; cvta.to.shared.u64 t, %1; cvt.u32.u64 %0, t; }":"=r"(a):"l"(p));
    return a;
}
__device__ __forceinline__ void split2(float f, bf& h, bf& l){
    h = __float2bfloat16(f);
    l = __float2bfloat16(f - __bfloat162float(h));
}
__device__ __forceinline__ void ldsm4(uint32_t* r, uint32_t a){
    asm volatile("ldmatrix.sync.aligned.m8n8.x4.shared.b16 {%0,%1,%2,%3}, [%4];"
        :"=r"(r[0]),"=r"(r[1]),"=r"(r[2]),"=r"(r[3]):"r"(a));
}
__device__ __forceinline__ void mma16816(float* d, const uint32_t* a, const uint32_t* b){
    asm volatile("mma.sync.aligned.m16n8k16.row.col.f32.bf16.bf16.f32 "
        "{%0,%1,%2,%3}, {%4,%5,%6,%7}, {%8,%9}, {%0,%1,%2,%3};"
        : "+f"(d[0]),"+f"(d[1]),"+f"(d[2]),"+f"(d[3])
        : "r"(a[0]),"r"(a[1]),"r"(a[2]),"r"(a[3]),"r"(b[0]),"r"(b[1]));
}
__device__ __forceinline__ void cpa(uint32_t dst, const void* src, uint32_t sz){
    asm volatile("cp.async.cg.shared.global [%0], [%1], 16, %2;"::"r"(dst),"l"(src),"r"(sz));
}

// smem layout per buffer (bytes): AH 0, AL 10240, BH 20480, BL 30720; row pitch 80B (40 bf16)
#define BUFB 40960

// ---------------- generic split-bf16 warp-MMA GEMM ---------------------------
// C[128 x NT] = A[128,K] @ Bt[NT,K]^T, K in chunks of 32.
// MODE 0 proj->hi/lo  1 qm->fp32(guard MREL)  2 logits->fp32(+rel,+mask)
// MODE 3 attn@V^T + wr@ev^T -> hi/lo          4 final+bias->fp32
template<int NT,int MODE,int NCH>
__global__ void __launch_bounds__(256,2) gemm_mma(
    const bf* __restrict__ A0h, const bf* __restrict__ A0l,
    const bf* __restrict__ B0h, const bf* __restrict__ B0l,
    const bf* __restrict__ A1h, const bf* __restrict__ A1l,
    const bf* __restrict__ B1h, const bf* __restrict__ B1l,
    float* __restrict__ cf, bf* __restrict__ ch, bf* __restrict__ cl,
    const float* __restrict__ qmv, const float* __restrict__ mask,
    const float* __restrict__ bias)
{
    constexpr int WN = NT/2;      // warp n-extent
    constexpr int NS = WN/8;      // n-subtiles per warp
    extern __shared__ char smc[];
    const uint32_t S = smem_u32(smc);
    const int t = threadIdx.x, lane = t&31, w = t>>5;
    const int wm = w>>1, wn = w&1;

    const int bh = blockIdx.z, b = bh>>4, h = bh&15;
    const int m0 = blockIdx.y*128, n0 = blockIdx.x*NT;

    const bf *Ah,*Al,*Bh,*Bl; int lda, ldb, vB;
    if (MODE==0 || MODE==4){
        Ah=A0h+(size_t)m0*Un; Al=A0l+(size_t)m0*Un;
        Bh=B0h+(size_t)n0*Un; Bl=B0l+(size_t)n0*Un; lda=Un; ldb=Un; vB=128;
    } else if (MODE==1){
        Ah=A0h+((size_t)((b<<10)+m0))*Un+(h<<6); Al=A0l+((size_t)((b<<10)+m0))*Un+(h<<6);
        Bh=B0h+(size_t)h*MREL*Dn+(size_t)n0*Dn;  Bl=B0l+(size_t)h*MREL*Dn+(size_t)n0*Dn;
        lda=Un; ldb=Dn; vB = MREL-n0 < 128 ? MREL-n0 : 128;
    } else if (MODE==2){
        Ah=A0h+((size_t)((b<<10)+m0))*Un+(h<<6); Al=A0l+((size_t)((b<<10)+m0))*Un+(h<<6);
        Bh=B0h+((size_t)((b<<10)+n0))*Un+(h<<6); Bl=B0l+((size_t)((b<<10)+n0))*Un+(h<<6);
        lda=Un; ldb=Un; vB=128;
    } else {
        Ah=A0h+(((size_t)((bh<<10)+m0))<<10); Al=A0l+(((size_t)((bh<<10)+m0))<<10);
        Bh=B0h+((size_t)bh<<16);              Bl=B0l+((size_t)bh<<16);
        lda=Ln; ldb=Ln; vB=64;
    }

    // ldmatrix per-thread geometry
    const int rA = lane&15,               kA = (lane>>4)*8;
    const int rB = (lane&7)+((lane>>4)<<3), kB = ((lane>>3)&1)*8;
    uint32_t aoff[2], boff[NS/2 > 0 ? NS/2 : 1];
    #pragma unroll
    for (int ms=0; ms<2; ms++) aoff[ms] = (uint32_t)((wm*32+ms*16+rA)*80 + kA*2);
    #pragma unroll
    for (int p4=0; p4<NS/2; p4++) boff[p4] = (uint32_t)(20480 + (wn*WN+p4*16+rB)*80 + kB*2);

    // chunk loader: 2048 x 16B cp.async (8 per thread)
    auto load_chunk = [&](int c, int p){
        const bf *gah,*gal,*gbh,*gbl; int la, lb, vb;
        if (MODE==3 && c>=32){
            int off=(c-32)*32;
            gah=A1h+((size_t)((bh<<10)+m0))*192+off; gal=A1l+((size_t)((bh<<10)+m0))*192+off;
            gbh=B1h+(size_t)h*Dn*192+off;            gbl=B1l+(size_t)h*Dn*192+off;
            la=192; lb=192; vb=64;
        } else {
            gah=Ah+c*32; gal=Al+c*32; gbh=Bh+c*32; gbl=Bl+c*32; la=lda; lb=ldb; vb=vB;
        }
        uint32_t sbase = S + p*BUFB;
        #pragma unroll
        for (int i=0;i<8;i++){
            int e = t + i*256;
            int isB = e >> 10;
            int e2 = e & 1023;
            int hl = e2 >> 9;
            int r  = (e2 >> 2) & 127;
            int sg = e2 & 3;
            const bf* gp; int ld, vr;
            if (!isB){ gp = hl? gal: gah; ld=la; vr=128; }
            else     { gp = hl? gbl: gbh; ld=lb; vr=vb; }
            int rs = r < vr ? r : 0;
            const bf* src = gp + (size_t)rs*ld + sg*8;
            uint32_t dst = sbase + (uint32_t)(isB*20480 + hl*10240 + r*80 + sg*16);
            cpa(dst, src, (r < vr) ? 16u : 0u);
        }
        asm volatile("cp.async.commit_group;" ::: "memory");
    };

    float acc[2][NS][4];
    #pragma unroll
    for (int ms=0;ms<2;ms++)
        #pragma unroll
        for (int ns=0;ns<NS;ns++)
            #pragma unroll
            for (int k=0;k<4;k++) acc[ms][ns][k] = 0.f;

    load_chunk(0, 0);
    for (int c = 0; c < NCH; c++){
        if (c+1 < NCH){
            load_chunk(c+1, (c+1)&1);
            asm volatile("cp.async.wait_group 1;" ::: "memory");
        } else {
            asm volatile("cp.async.wait_group 0;" ::: "memory");
        }
        __syncthreads();
        uint32_t base = S + (c&1)*BUFB;
        #pragma unroll
        for (int k16=0;k16<2;k16++){
            uint32_t ah2[2][4], al2[2][4];
            #pragma unroll
            for (int ms=0;ms<2;ms++){
                ldsm4(ah2[ms], base + aoff[ms] + k16*32);
                ldsm4(al2[ms], base + aoff[ms] + k16*32 + 10240);
            }
            #pragma unroll
            for (int p4=0;p4<NS/2;p4++){
                uint32_t bh4[4], bl4[4];
                ldsm4(bh4, base + boff[p4] + k16*32);
                ldsm4(bl4, base + boff[p4] + k16*32 + 10240);
                #pragma unroll
                for (int ms=0;ms<2;ms++){
                    mma16816(acc[ms][2*p4],   ah2[ms], bh4);
                    mma16816(acc[ms][2*p4+1], ah2[ms], bh4+2);
                    mma16816(acc[ms][2*p4],   al2[ms], bh4);
                    mma16816(acc[ms][2*p4+1], al2[ms], bh4+2);
                    mma16816(acc[ms][2*p4],   ah2[ms], bl4);
                    mma16816(acc[ms][2*p4+1], ah2[ms], bl4+2);
                }
            }
        }
        __syncthreads();
    }

    // -------- epilogue --------
    const int lr = lane>>2, lc = (lane&3)<<1;
    #pragma unroll
    for (int ms=0;ms<2;ms++){
        #pragma unroll
        for (int ns=0;ns<NS;ns++){
            const int rt = wm*32 + ms*16 + lr;
            const int ct = wn*WN + ns*8 + lc;
            float* a = acc[ms][ns];
            if (MODE==0 || MODE==3){
                size_t d0;
                if (MODE==0) d0 = (size_t)(m0+rt)*Un + n0 + ct;
                else         d0 = ((size_t)((b<<10)+m0+rt))*Un + (h<<6) + ct;
                __nv_bfloat162 hv, lv;
                split2(a[0], hv.x, lv.x); split2(a[1], hv.y, lv.y);
                *(__nv_bfloat162*)(ch+d0) = hv; *(__nv_bfloat162*)(cl+d0) = lv;
                split2(a[2], hv.x, lv.x); split2(a[3], hv.y, lv.y);
                *(__nv_bfloat162*)(ch+d0+(size_t)8*Un) = hv;
                *(__nv_bfloat162*)(cl+d0+(size_t)8*Un) = lv;
            } else if (MODE==4){
                const int R = m0+rt, C = n0+ct;
                float2 v;
                v.x = a[0]+bias[C]; v.y = a[1]+bias[C+1];
                *(float2*)(cf+(size_t)R*Un+C) = v;
                v.x = a[2]+bias[C]; v.y = a[3]+bias[C+1];
                *(float2*)(cf+(size_t)(R+8)*Un+C) = v;
            } else if (MODE==1){
                const int R = m0+rt, j = n0+ct;
                size_t b0r = ((size_t)((bh<<10)+R))*MREL;
                size_t b8r = ((size_t)((bh<<10)+R+8))*MREL;
                if (j   < MREL){ cf[b0r+j]   = a[0]; cf[b8r+j]   = a[2]; }
                if (j+1 < MREL){ cf[b0r+j+1] = a[1]; cf[b8r+j+1] = a[3]; }
            } else { // MODE 2
                const int j = n0+ct;
                const float mk0 = mask[(b<<10)+j]   * -1e9f;
                const float mk1 = mask[(b<<10)+j+1] * -1e9f;
                #pragma unroll
                for (int half=0; half<2; half++){
                    const int i = m0 + rt + half*8;
                    const float* qrow = qmv + ((size_t)((bh<<10)+i))*MREL;
                    int o0 = j - i;   o0 = o0 < -64 ? -64 : (o0 > 64 ? 64 : o0);
                    int o1 = j+1 - i; o1 = o1 < -64 ? -64 : (o1 > 64 ? 64 : o1);
                    float2 v;
                    v.x = (a[half*2+0] + qrow[o0+64])*SCALE + mk0;
                    v.y = (a[half*2+1] + qrow[o1+64])*SCALE + mk1;
                    *(float2*)(cf + (((size_t)((bh<<10)+i))<<10) + j) = v;
                }
            }
        }
    }
}

// ---------------- prep kernels ----------------------------------------------
__global__ void conv_hl(const float* __restrict__ x, bf* __restrict__ h, bf* __restrict__ l, int n4){
    int i = blockIdx.x*256 + threadIdx.x;
    if (i >= n4) return;
    float4 v = ((const float4*)x)[i];
    bf hb[4], lb[4];
    split2(v.x, hb[0], lb[0]); split2(v.y, hb[1], lb[1]);
    split2(v.z, hb[2], lb[2]); split2(v.w, hb[3], lb[3]);
    ((uint2*)h)[i] = *(uint2*)hb;
    ((uint2*)l)[i] = *(uint2*)lb;
}

__global__ void convT(const float* __restrict__ w, bf* __restrict__ oh, bf* __restrict__ ol){
    __shared__ float tl[32][33];
    const int n0 = blockIdx.x*32, k0 = blockIdx.y*32;
    const int tx = threadIdx.x, ty = threadIdx.y;
    for (int yy = 0; yy < 32; yy += 8)
        tl[ty+yy][tx] = w[(size_t)(k0+ty+yy)*Un + n0+tx];
    __syncthreads();
    for (int yy = 0; yy < 32; yy += 8){
        float f = tl[tx][ty+yy];
        bf hb, lb; split2(f, hb, lb);
        size_t dst = (size_t)(n0+ty+yy)*Un + k0+tx;
        oh[dst] = hb; ol[dst] = lb;
    }
}

__global__ void evT_prep(const float* __restrict__ ev){
    int hh = blockIdx.x;
    for (int v = threadIdx.x; v < Dn*192; v += 256){
        int d = v/192, m = v%192;
        float f = (m < MREL) ? ev[(size_t)hh*MREL*Dn + (size_t)m*Dn + d] : 0.f;
        bf hb, lb; split2(f, hb, lb);
        g_evth[(size_t)hh*Dn*192 + v] = hb;
        g_evtl[(size_t)hh*Dn*192 + v] = lb;
    }
}

__global__ void vtr(){   // [b,l,u] -> [bh,d,l]
    __shared__ bf th[64][65], tl2[64][65];
    const int bh = blockIdx.y, b = bh>>4, hh = bh&15, l0 = blockIdx.x*64;
    for (int v = threadIdx.x; v < 64*64; v += 256){
        int r = v>>6, d = v&63;
        size_t src = ((size_t)((b<<10)+l0+r))*Un + (hh<<6) + d;
        th[d][r] = g_vh[src]; tl2[d][r] = g_vl[src];
    }
    __syncthreads();
    for (int v = threadIdx.x; v < 64*64; v += 256){
        int d = v>>6, r = v&63;
        size_t dst = (((size_t)((bh<<6)+d))<<10) + l0 + r;
        g_vth[dst] = th[d][r]; g_vtl[dst] = tl2[d][r];
    }
}

// ---------------- fused softmax + bf16 emit + relative-bucket wr -------------
__global__ void __launch_bounds__(256) softmax_k(){
    const int gid = blockIdx.x;            // (bh<<10)+i
    const int i = gid & 1023;
    float* p = g_logit + ((size_t)gid<<10);
    const int t = threadIdx.x, lane = t&31, w = t>>5;
    __shared__ float ps[1024];
    __shared__ float red[8], rl[8], rh[8], wr[MREL];

    float v0 = p[t], v1 = p[t+256], v2 = p[t+512], v3 = p[t+768];
    float m = fmaxf(fmaxf(v0,v1), fmaxf(v2,v3));
    #pragma unroll
    for (int o=16;o;o>>=1) m = fmaxf(m, __shfl_xor_sync(0xffffffffu, m, o));
    if (lane==0) red[w] = m;
    __syncthreads();
    if (t==0){ float mm=red[0]; for(int k=1;k<8;k++) mm=fmaxf(mm,red[k]); red[0]=mm; }
    __syncthreads();
    const float rm = red[0];
    v0 = __expf(v0-rm); v1 = __expf(v1-rm); v2 = __expf(v2-rm); v3 = __expf(v3-rm);
    float s = v0+v1+v2+v3;
    #pragma unroll
    for (int o=16;o;o>>=1) s += __shfl_xor_sync(0xffffffffu, s, o);
    if (lane==0) rl[w] = s;
    __syncthreads();
    if (t==0){ float tt=0.f; for(int k=0;k<8;k++) tt+=rl[k]; red[0]=tt; }
    __syncthreads();
    const float inv = 1.0f/red[0];
    v0*=inv; v1*=inv; v2*=inv; v3*=inv;
    ps[t]=v0; ps[t+256]=v1; ps[t+512]=v2; ps[t+768]=v3;

    const size_t ro = (size_t)gid<<10;
    bf hb, lb;
    split2(v0,hb,lb); g_ah[ro+t]=hb;     g_al[ro+t]=lb;
    split2(v1,hb,lb); g_ah[ro+t+256]=hb; g_al[ro+t+256]=lb;
    split2(v2,hb,lb); g_ah[ro+t+512]=hb; g_al[ro+t+512]=lb;
    split2(v3,hb,lb); g_ah[ro+t+768]=hb; g_al[ro+t+768]=lb;
    __syncthreads();

    if (t >= 1 && t <= 127){
        int j = i + t - 64;
        wr[t] = (j>=0 && j<Ln) ? ps[j] : 0.f;
    }
    float lo = 0.f, hi2 = 0.f;
    for (int j = t;      j <= i-64; j += 256) lo  += ps[j];
    for (int j = i+64+t; j <  Ln;   j += 256) hi2 += ps[j];
    #pragma unroll
    for (int o=16;o;o>>=1){
        lo  += __shfl_xor_sync(0xffffffffu, lo, o);
        hi2 += __shfl_xor_sync(0xffffffffu, hi2, o);
    }
    if (lane==0){ rl[w]=lo; rh[w]=hi2; }
    __syncthreads();
    if (t==0) { float a=0; for(int k=0;k<8;k++) a+=rl[k]; wr[0]=a; }
    if (t==32){ float a=0; for(int k=0;k<8;k++) a+=rh[k]; wr[128]=a; }
    __syncthreads();
    for (int mm = t; mm < 192; mm += 256){
        float f = (mm < MREL) ? wr[mm] : 0.f;
        split2(f,hb,lb);
        g_wrh[(size_t)gid*192+mm]=hb; g_wrl[(size_t)gid*192+mm]=lb;
    }
}

// -----------------------------------------------------------------------------
#define SMEMB (2*BUFB)

extern "C" void kernel_launch(void* const* d_in, const int* in_sizes, int n_in,
                              void* d_out, int out_size)
{
    const float* x    = (const float*)d_in[0];
    const float* mask = (const float*)d_in[1];
    const float* wq   = (const float*)d_in[2];
    const float* wk   = (const float*)d_in[3];
    const float* wv   = (const float*)d_in[4];
    const float* wo   = (const float*)d_in[5];
    const float* bo   = (const float*)d_in[6];
    const float* ek   = (const float*)d_in[7];
    const float* ev   = (const float*)d_in[8];
    float* out = (float*)d_out;

    bf *xh,*xl,*wth,*wtl,*ekh,*ekl,*evth,*evtl,*qh,*ql,*kh,*kl,*vh,*vl,*vth,*vtl;
    bf *ah,*al,*wrh,*wrl,*oh,*ol;
    float *qm,*logit;
    cudaGetSymbolAddress((void**)&xh, g_xh);     cudaGetSymbolAddress((void**)&xl, g_xl);
    cudaGetSymbolAddress((void**)&wth, g_wth);   cudaGetSymbolAddress((void**)&wtl, g_wtl);
    cudaGetSymbolAddress((void**)&ekh, g_ekh);   cudaGetSymbolAddress((void**)&ekl, g_ekl);
    cudaGetSymbolAddress((void**)&evth, g_evth); cudaGetSymbolAddress((void**)&evtl, g_evtl);
    cudaGetSymbolAddress((void**)&qh, g_qh);     cudaGetSymbolAddress((void**)&ql, g_ql);
    cudaGetSymbolAddress((void**)&kh, g_kh);     cudaGetSymbolAddress((void**)&kl, g_kl);
    cudaGetSymbolAddress((void**)&vh, g_vh);     cudaGetSymbolAddress((void**)&vl, g_vl);
    cudaGetSymbolAddress((void**)&vth, g_vth);   cudaGetSymbolAddress((void**)&vtl, g_vtl);
    cudaGetSymbolAddress((void**)&ah, g_ah);     cudaGetSymbolAddress((void**)&al, g_al);
    cudaGetSymbolAddress((void**)&wrh, g_wrh);   cudaGetSymbolAddress((void**)&wrl, g_wrl);
    cudaGetSymbolAddress((void**)&oh, g_oh);     cudaGetSymbolAddress((void**)&ol, g_ol);
    cudaGetSymbolAddress((void**)&qm, g_qm);     cudaGetSymbolAddress((void**)&logit, g_logit);

    cudaFuncSetAttribute(gemm_mma<128,0,32>, cudaFuncAttributeMaxDynamicSharedMemorySize, SMEMB);
    cudaFuncSetAttribute(gemm_mma<128,1,2>,  cudaFuncAttributeMaxDynamicSharedMemorySize, SMEMB);
    cudaFuncSetAttribute(gemm_mma<128,2,2>,  cudaFuncAttributeMaxDynamicSharedMemorySize, SMEMB);
    cudaFuncSetAttribute(gemm_mma<64,3,38>,  cudaFuncAttributeMaxDynamicSharedMemorySize, SMEMB);
    cudaFuncSetAttribute(gemm_mma<128,4,32>, cudaFuncAttributeMaxDynamicSharedMemorySize, SMEMB);

    // prep: split into bf16 hi/lo
    conv_hl<<<(Bn*Ln*Un/4+255)/256, 256>>>(x, xh, xl, Bn*Ln*Un/4);
    convT<<<dim3(32,32), dim3(32,8)>>>(wq, wth+0*Un*Un, wtl+0*Un*Un);
    convT<<<dim3(32,32), dim3(32,8)>>>(wk, wth+1*Un*Un, wtl+1*Un*Un);
    convT<<<dim3(32,32), dim3(32,8)>>>(wv, wth+2*Un*Un, wtl+2*Un*Un);
    convT<<<dim3(32,32), dim3(32,8)>>>(wo, wth+3*Un*Un, wtl+3*Un*Un);
    conv_hl<<<(Hn*MREL*Dn/4+255)/256, 256>>>(ek, ekh, ekl, Hn*MREL*Dn/4);
    evT_prep<<<Hn, 256>>>(ev);

    // Q/K/V projections
    const dim3 gp(Un/128, (Bn*Ln)/128, 1);
    gemm_mma<128,0,32><<<gp,256,SMEMB>>>(xh,xl, wth+0*Un*Un,wtl+0*Un*Un, 0,0,0,0, 0, qh,ql, 0,0,0);
    gemm_mma<128,0,32><<<gp,256,SMEMB>>>(xh,xl, wth+1*Un*Un,wtl+1*Un*Un, 0,0,0,0, 0, kh,kl, 0,0,0);
    gemm_mma<128,0,32><<<gp,256,SMEMB>>>(xh,xl, wth+2*Un*Un,wtl+2*Un*Un, 0,0,0,0, 0, vh,vl, 0,0,0);
    vtr<<<dim3(16,BHn), 256>>>();

    // qm = Q . ek^T
    gemm_mma<128,1,2><<<dim3(2,8,BHn),256,SMEMB>>>(qh,ql, ekh,ekl, 0,0,0,0, qm, 0,0, 0,0,0);

    // logits = (QK^T + rel)*scale + mask
    gemm_mma<128,2,2><<<dim3(8,8,BHn),256,SMEMB>>>(qh,ql, kh,kl, 0,0,0,0, logit, 0,0, qm, mask, 0);

    // softmax + attn bf16 emit + wr buckets
    softmax_k<<<BHn*Ln, 256>>>();

    // O = attn@V^T + wr@ev^T
    gemm_mma<64,3,38><<<dim3(1,8,BHn),256,SMEMB>>>(ah,al, vth,vtl, wrh,wrl, evth,evtl, 0, oh,ol, 0,0,0);

    // out = O @ Wo^T + bo
    gemm_mma<128,4,32><<<gp,256,SMEMB>>>(oh,ol, wth+3*Un*Un,wtl+3*Un*Un, 0,0,0,0, out, 0,0, 0,0, bo);
}